// round 2
// baseline (speedup 1.0000x reference)
#include <cuda_runtime.h>
#include <math.h>

#define NQ 8192
#define MK 8192
#define DD 128
#define BM 64
#define BN 64
#define NSPLIT 8
#define ROWS_PER_SPLIT (NQ / NSPLIT)   // 1024

// pad-68 float rows: 68*4=272 bytes, 16B aligned, conflict-free for float4 LDS
#define QK_STRIDE 68
#define V_STRIDE 132

__device__ float g_pmax[NSPLIT][MK];
__device__ float g_psum[NSPLIT][MK];
__device__ float g_cadj[MK];

// ---------------------------------------------------------------------------
// Kernel 1: per-column (key) partial softmax stats over a slice of queries.
// Each block: 64 key columns x 1024 query rows. Online max/sum across 16
// chunks of 64 rows. 4x4 register microtile per thread (16x16 threads).
// ---------------------------------------------------------------------------
__global__ __launch_bounds__(256, 1)
void colstats_kernel(const float* __restrict__ Q, const float* __restrict__ K) {
    extern __shared__ float sm[];
    float* Qs = sm;                   // [128][68] transposed: Qs[d][n]
    float* Ks = sm + DD * QK_STRIDE;  // [128][68] transposed: Ks[d][m]
    __shared__ float red[BM][17];
    __shared__ float runmax[BM];
    __shared__ float runsum[BM];
    __shared__ float newmax[BM];

    const int m0    = blockIdx.x * BM;
    const int nbase = blockIdx.y * ROWS_PER_SPLIT;
    const int tid   = threadIdx.x;
    const int tx    = tid & 15;
    const int ty    = tid >> 4;

    // Load K tile transposed (coalesced global reads)
    #pragma unroll
    for (int i = 0; i < (BM * DD) / 256; i++) {
        int idx = tid + i * 256;
        int m = idx >> 7;
        int d = idx & 127;
        Ks[d * QK_STRIDE + m] = K[(m0 + m) * DD + d];
    }
    if (tid < BM) { runmax[tid] = -1e30f; runsum[tid] = 0.0f; }

    for (int nc = 0; nc < ROWS_PER_SPLIT; nc += BN) {
        const int n0 = nbase + nc;
        __syncthreads();  // prior-iter readers done / K load visible
        #pragma unroll
        for (int i = 0; i < (BN * DD) / 256; i++) {
            int idx = tid + i * 256;
            int n = idx >> 7;
            int d = idx & 127;
            Qs[d * QK_STRIDE + n] = Q[(n0 + n) * DD + d];
        }
        __syncthreads();

        float acc[4][4];
        #pragma unroll
        for (int i = 0; i < 4; i++)
            #pragma unroll
            for (int j = 0; j < 4; j++) acc[i][j] = 0.0f;

        #pragma unroll 8
        for (int k = 0; k < DD; k++) {
            float4 a4 = *(const float4*)(Qs + k * QK_STRIDE + ty * 4);
            float4 b4 = *(const float4*)(Ks + k * QK_STRIDE + tx * 4);
            float av[4] = {a4.x, a4.y, a4.z, a4.w};
            float bv[4] = {b4.x, b4.y, b4.z, b4.w};
            #pragma unroll
            for (int i = 0; i < 4; i++)
                #pragma unroll
                for (int j = 0; j < 4; j++)
                    acc[i][j] += av[i] * bv[j];
        }

        // column-wise local max
        #pragma unroll
        for (int j = 0; j < 4; j++) {
            float mx = acc[0][j];
            #pragma unroll
            for (int i = 1; i < 4; i++) mx = fmaxf(mx, acc[i][j]);
            red[tx * 4 + j][ty] = mx;
        }
        __syncthreads();
        if (tid < BM) {
            float mx = red[tid][0];
            #pragma unroll
            for (int s = 1; s < 16; s++) mx = fmaxf(mx, red[tid][s]);
            float old = runmax[tid];
            float nm  = fmaxf(old, mx);
            newmax[tid] = nm;
            runsum[tid] *= __expf(old - nm);
            runmax[tid] = nm;
        }
        __syncthreads();
        // column-wise local sumexp against new max
        #pragma unroll
        for (int j = 0; j < 4; j++) {
            float nm = newmax[tx * 4 + j];
            float s = 0.0f;
            #pragma unroll
            for (int i = 0; i < 4; i++) s += __expf(acc[i][j] - nm);
            red[tx * 4 + j][ty] = s;
        }
        __syncthreads();
        if (tid < BM) {
            float s = 0.0f;
            #pragma unroll
            for (int k = 0; k < 16; k++) s += red[tid][k];
            runsum[tid] += s;
        }
    }
    __syncthreads();
    if (tid < BM) {
        g_pmax[blockIdx.y][m0 + tid] = runmax[tid];
        g_psum[blockIdx.y][m0 + tid] = runsum[tid];
    }
}

// ---------------------------------------------------------------------------
// Kernel 2: combine the NSPLIT partials into cadj[m] = max + log(sumexp)
// ---------------------------------------------------------------------------
__global__ void combine_kernel() {
    int m = blockIdx.x * blockDim.x + threadIdx.x;
    if (m >= MK) return;
    float gmax = -1e30f;
    #pragma unroll
    for (int s = 0; s < NSPLIT; s++) gmax = fmaxf(gmax, g_pmax[s][m]);
    float tot = 0.0f;
    #pragma unroll
    for (int s = 0; s < NSPLIT; s++)
        tot += g_psum[s][m] * __expf(g_pmax[s][m] - gmax);
    g_cadj[m] = gmax + __logf(tot);
}

// ---------------------------------------------------------------------------
// Kernel 3: out[n,:] = sum_m exp(Q[n]·K[m] - cadj[m]) * V[m,:]
// Each block: 64 query rows x full D=128 output, looping over key chunks.
// ---------------------------------------------------------------------------
__global__ __launch_bounds__(256, 1)
void out_kernel(const float* __restrict__ Q, const float* __restrict__ K,
                const float* __restrict__ V, float* __restrict__ out) {
    extern __shared__ float sm[];
    float* Qs = sm;                       // [128][68] Qs[d][n]
    float* Ks = Qs + DD * QK_STRIDE;      // [128][68] Ks[d][m]
    float* Vs = Ks + DD * QK_STRIDE;      // [64][132] Vs[m][d]
    float* Ps = Vs + BM * V_STRIDE;       // [64][68]  Ps[m][n]
    __shared__ float cadj_s[BM];

    const int n0  = blockIdx.x * BN;
    const int tid = threadIdx.x;
    const int tx  = tid & 15;
    const int ty  = tid >> 4;

    #pragma unroll
    for (int i = 0; i < (BN * DD) / 256; i++) {
        int idx = tid + i * 256;
        int n = idx >> 7;
        int d = idx & 127;
        Qs[d * QK_STRIDE + n] = Q[(n0 + n) * DD + d];
    }

    float oacc[4][8];
    #pragma unroll
    for (int i = 0; i < 4; i++)
        #pragma unroll
        for (int j = 0; j < 8; j++) oacc[i][j] = 0.0f;

    for (int mc = 0; mc < MK; mc += BM) {
        __syncthreads();  // prior-iter Ps/Vs readers done; Q load visible 1st iter
        #pragma unroll
        for (int i = 0; i < (BM * DD) / 256; i++) {
            int idx = tid + i * 256;
            int m = idx >> 7;
            int d = idx & 127;
            Ks[d * QK_STRIDE + m] = K[(mc + m) * DD + d];
            Vs[m * V_STRIDE + d]  = V[(mc + m) * DD + d];
        }
        if (tid < BM) cadj_s[tid] = g_cadj[mc + tid];
        __syncthreads();

        // QK^T 64x64 tile
        float acc[4][4];
        #pragma unroll
        for (int i = 0; i < 4; i++)
            #pragma unroll
            for (int j = 0; j < 4; j++) acc[i][j] = 0.0f;

        #pragma unroll 8
        for (int k = 0; k < DD; k++) {
            float4 a4 = *(const float4*)(Qs + k * QK_STRIDE + ty * 4);
            float4 b4 = *(const float4*)(Ks + k * QK_STRIDE + tx * 4);
            float av[4] = {a4.x, a4.y, a4.z, a4.w};
            float bv[4] = {b4.x, b4.y, b4.z, b4.w};
            #pragma unroll
            for (int i = 0; i < 4; i++)
                #pragma unroll
                for (int j = 0; j < 4; j++)
                    acc[i][j] += av[i] * bv[j];
        }

        // p = exp(s - cadj[m]), stored transposed Ps[m][n]
        #pragma unroll
        for (int j = 0; j < 4; j++) {
            float c = cadj_s[tx * 4 + j];
            #pragma unroll
            for (int i = 0; i < 4; i++)
                Ps[(tx * 4 + j) * QK_STRIDE + ty * 4 + i] = __expf(acc[i][j] - c);
        }
        __syncthreads();

        // PV: oacc[n=ty*4.., d=tx*8..] += P[n][m] * V[m][d]
        #pragma unroll 4
        for (int m = 0; m < BM; m++) {
            float4 p4 = *(const float4*)(Ps + m * QK_STRIDE + ty * 4);
            float pv[4] = {p4.x, p4.y, p4.z, p4.w};
            float4 v0 = *(const float4*)(Vs + m * V_STRIDE + tx * 8);
            float4 v1 = *(const float4*)(Vs + m * V_STRIDE + tx * 8 + 4);
            float vv[8] = {v0.x, v0.y, v0.z, v0.w, v1.x, v1.y, v1.z, v1.w};
            #pragma unroll
            for (int i = 0; i < 4; i++)
                #pragma unroll
                for (int d = 0; d < 8; d++)
                    oacc[i][d] += pv[i] * vv[d];
        }
    }

    #pragma unroll
    for (int i = 0; i < 4; i++) {
        int row = n0 + ty * 4 + i;
        float4 r0 = make_float4(oacc[i][0], oacc[i][1], oacc[i][2], oacc[i][3]);
        float4 r1 = make_float4(oacc[i][4], oacc[i][5], oacc[i][6], oacc[i][7]);
        *(float4*)(out + row * DD + tx * 8)     = r0;
        *(float4*)(out + row * DD + tx * 8 + 4) = r1;
    }
}

// ---------------------------------------------------------------------------
extern "C" void kernel_launch(void* const* d_in, const int* in_sizes, int n_in,
                              void* d_out, int out_size) {
    (void)in_sizes; (void)n_in; (void)out_size;
    const float* Q = (const float*)d_in[0];
    const float* K = (const float*)d_in[1];
    const float* V = (const float*)d_in[2];
    float* out = (float*)d_out;

    const size_t smemA = (size_t)(2 * DD * QK_STRIDE) * sizeof(float);            // 69,632 B
    const size_t smemC = (size_t)(2 * DD * QK_STRIDE + BM * V_STRIDE + BM * QK_STRIDE) * sizeof(float); // 120,832 B

    cudaFuncSetAttribute(colstats_kernel, cudaFuncAttributeMaxDynamicSharedMemorySize, (int)smemA);
    cudaFuncSetAttribute(out_kernel,      cudaFuncAttributeMaxDynamicSharedMemorySize, (int)smemC);

    colstats_kernel<<<dim3(MK / BM, NSPLIT), 256, smemA>>>(Q, K);
    combine_kernel<<<MK / 256, 256>>>();
    out_kernel<<<NQ / BN, 256, smemC>>>(Q, K, V, out);
}

// round 6
// speedup vs baseline: 3.3142x; 3.3142x over previous
#include <cuda_runtime.h>
#include <cuda_bf16.h>
#include <cstdint>

#define SEQ 8192
#define HD  128

__device__ __align__(256) __nv_bfloat16 g_Qh[SEQ * HD];
__device__ __align__(256) __nv_bfloat16 g_Ql[SEQ * HD];
__device__ __align__(256) __nv_bfloat16 g_Kh[SEQ * HD];
__device__ __align__(256) __nv_bfloat16 g_Kl[SEQ * HD];
__device__ __align__(256) __nv_bfloat16 g_Vth[HD * SEQ];   // V^T hi: [d][m]
__device__ __align__(256) __nv_bfloat16 g_Vtl[HD * SEQ];   // V^T lo
__device__ __align__(8) float g_pmax[2][SEQ];
__device__ __align__(8) float g_psum[2][SEQ];
__device__ __align__(8) float g_cadj[SEQ];
__device__ __align__(16) float g_part[2][SEQ * HD];

__device__ __forceinline__ uint32_t smem_u32(const void* p) {
    uint32_t a;
    asm("{ .reg .u64 t; cvta.to.shared.u64 t, %1; cvt.u32.u64 %0, t; }" : "=r"(a) : "l"(p));
    return a;
}
#define CP16(dst, src) asm volatile("cp.async.cg.shared.global [%0], [%1], 16;" :: "r"(dst), "l"(src))
#define CP_COMMIT()    asm volatile("cp.async.commit_group;" ::: "memory")
#define CP_WAIT0()     asm volatile("cp.async.wait_group 0;" ::: "memory")
#define CP_WAIT1()     asm volatile("cp.async.wait_group 1;" ::: "memory")

#define LDSM4(r, addr) \
    asm volatile("ldmatrix.sync.aligned.m8n8.x4.shared.b16 {%0,%1,%2,%3}, [%4];" \
        : "=r"((r)[0]), "=r"((r)[1]), "=r"((r)[2]), "=r"((r)[3]) : "r"(addr))

#define MMA(c, a, b0, b1) \
    asm volatile("mma.sync.aligned.m16n8k16.row.col.f32.bf16.bf16.f32 " \
        "{%0,%1,%2,%3},{%4,%5,%6,%7},{%8,%9},{%0,%1,%2,%3};" \
        : "+f"((c)[0]), "+f"((c)[1]), "+f"((c)[2]), "+f"((c)[3]) \
        : "r"((a)[0]), "r"((a)[1]), "r"((a)[2]), "r"((a)[3]), "r"(b0), "r"(b1))

// row stride for 128-col bf16 tiles: 256B data + 16B pad
#define ST128 272u
// row stride for 32-col bf16 tiles: 64B data + 16B pad
#define ST32  80u

// [rows x 128 bf16] gmem (row stride HD) -> smem stride ST128
__device__ __forceinline__ void cp128(uint32_t dst, const __nv_bfloat16* g, int rows, int tid) {
    for (int i = tid; i < rows * 16; i += 256) {
        int r = i >> 4, c = i & 15;
        CP16(dst + (uint32_t)r * ST128 + (uint32_t)c * 16, g + r * HD + c * 8);
    }
}
// [128 x 32 bf16] gmem (row stride SEQ) -> smem stride ST32
__device__ __forceinline__ void cpV(uint32_t dst, const __nv_bfloat16* g, int tid) {
    for (int i = tid; i < 512; i += 256) {
        int r = i >> 2, c = i & 3;
        CP16(dst + (uint32_t)r * ST32 + (uint32_t)c * 16, g + r * SEQ + c * 8);
    }
}

// ============================ converts ======================================
__global__ void conv_qk_kernel(const float* __restrict__ Q, const float* __restrict__ K) {
    int i = blockIdx.x * blockDim.x + threadIdx.x;
    if (i >= SEQ * HD) return;
    float q = Q[i];
    __nv_bfloat16 qh = __float2bfloat16_rn(q);
    g_Qh[i] = qh; g_Ql[i] = __float2bfloat16_rn(q - __bfloat162float(qh));
    float k = K[i];
    __nv_bfloat16 kh = __float2bfloat16_rn(k);
    g_Kh[i] = kh; g_Kl[i] = __float2bfloat16_rn(k - __bfloat162float(kh));
}
__global__ void conv_v_kernel(const float* __restrict__ V) {
    __shared__ float sv[64 * HD];
    int m0 = blockIdx.x * 64;
    for (int i = threadIdx.x; i < 64 * HD; i += 128) sv[i] = V[m0 * HD + i];
    __syncthreads();
    for (int i = threadIdx.x; i < 64 * HD; i += 128) {
        int d = i >> 6, j = i & 63;
        float v = sv[j * HD + d];
        __nv_bfloat16 h = __float2bfloat16_rn(v);
        g_Vth[d * SEQ + m0 + j] = h;
        g_Vtl[d * SEQ + m0 + j] = __float2bfloat16_rn(v - __bfloat162float(h));
    }
}

// ============================ pass A ========================================
// grid(64,2): 128 keys x 4096 queries. A = K rows (persistent frags), stream
// 32-query chunks (2-stage). Per-thread online (max,sumexp) for 2 key rows.
#define PA_K      0u
#define PA_K_LO   34816u                  // 128*272
#define PA_Q      69632u
#define PA_QSTG   17408u                  // 32*272*2 (hi+lo) per stage
#define PA_Q_LO   8704u                   // 32*272
#define PA_SMEM   (69632 + 2 * 17408)     // 104448

__global__ __launch_bounds__(256, 1)
void passA_kernel() {
    extern __shared__ char sm[];
    const uint32_t s0 = smem_u32(sm);
    const int tid = threadIdx.x, wid = tid >> 5, lane = tid & 31;
    const int m0 = blockIdx.x * 128, qbase = blockIdx.y * 4096;

    cp128(s0 + PA_K,           g_Kh + m0 * HD, 128, tid);
    cp128(s0 + PA_K + PA_K_LO, g_Kl + m0 * HD, 128, tid);
    CP_COMMIT();
    cp128(s0 + PA_Q,           g_Qh + qbase * HD, 32, tid);
    cp128(s0 + PA_Q + PA_Q_LO, g_Ql + qbase * HD, 32, tid);
    CP_COMMIT();
    CP_WAIT1();
    __syncthreads();

    // persistent A (K) fragments
    uint32_t Ah[8][4], Al[8][4];
    {
        uint32_t arow = (uint32_t)(wid * 16 + (lane & 7) + ((lane >> 3) & 1) * 8);
        uint32_t acol = (uint32_t)((lane >> 4) * 8);
        #pragma unroll
        for (int k = 0; k < 8; k++) {
            uint32_t a = s0 + PA_K + arow * ST128 + (k * 16 + acol) * 2;
            LDSM4(Ah[k], a);
            LDSM4(Al[k], a + PA_K_LO);
        }
    }

    float rm0 = -1e30f, rs0 = 0.0f, rm1 = -1e30f, rs1 = 0.0f;

    for (int ch = 0; ch < 128; ch++) {
        if (ch < 127) {
            uint32_t qb = s0 + PA_Q + (uint32_t)((ch + 1) & 1) * PA_QSTG;
            cp128(qb,           g_Qh + (qbase + (ch + 1) * 32) * HD, 32, tid);
            cp128(qb + PA_Q_LO, g_Ql + (qbase + (ch + 1) * 32) * HD, 32, tid);
            CP_COMMIT();
            CP_WAIT1();
        } else CP_WAIT0();
        __syncthreads();

        const uint32_t qb = s0 + PA_Q + (uint32_t)(ch & 1) * PA_QSTG;
        #pragma unroll
        for (int ns = 0; ns < 4; ns++) {
            float c[4] = {0.f, 0.f, 0.f, 0.f};
            #pragma unroll
            for (int kk = 0; kk < 4; kk++) {
                uint32_t Bh[4], Bl[4];
                uint32_t ba = qb + (uint32_t)(ns * 8 + (lane & 7)) * ST128
                                 + (uint32_t)(kk * 32 + ((lane >> 3) & 3) * 8) * 2;
                LDSM4(Bh, ba);
                LDSM4(Bl, ba + PA_Q_LO);
                MMA(c, Ah[2*kk],   Bh[0], Bh[1]);
                MMA(c, Al[2*kk],   Bh[0], Bh[1]);
                MMA(c, Ah[2*kk],   Bl[0], Bl[1]);
                MMA(c, Ah[2*kk+1], Bh[2], Bh[3]);
                MMA(c, Al[2*kk+1], Bh[2], Bh[3]);
                MMA(c, Ah[2*kk+1], Bl[2], Bl[3]);
            }
            float nm0 = fmaxf(rm0, fmaxf(c[0], c[1]));
            rs0 = rs0 * __expf(rm0 - nm0) + __expf(c[0] - nm0) + __expf(c[1] - nm0);
            rm0 = nm0;
            float nm1 = fmaxf(rm1, fmaxf(c[2], c[3]));
            rs1 = rs1 * __expf(rm1 - nm1) + __expf(c[2] - nm1) + __expf(c[3] - nm1);
            rm1 = nm1;
        }
        __syncthreads();
    }

    // merge the 4 lanes sharing each S^T row
    #pragma unroll
    for (int off = 1; off <= 2; off <<= 1) {
        float om = __shfl_xor_sync(0xffffffffu, rm0, off);
        float os = __shfl_xor_sync(0xffffffffu, rs0, off);
        float nm = fmaxf(rm0, om);
        rs0 = rs0 * __expf(rm0 - nm) + os * __expf(om - nm);
        rm0 = nm;
        om = __shfl_xor_sync(0xffffffffu, rm1, off);
        os = __shfl_xor_sync(0xffffffffu, rs1, off);
        nm = fmaxf(rm1, om);
        rs1 = rs1 * __expf(rm1 - nm) + os * __expf(om - nm);
        rm1 = nm;
    }
    if ((lane & 3) == 0) {
        int r = m0 + wid * 16 + (lane >> 2);
        g_pmax[blockIdx.y][r] = rm0;     g_psum[blockIdx.y][r] = rs0;
        g_pmax[blockIdx.y][r + 8] = rm1; g_psum[blockIdx.y][r + 8] = rs1;
    }
}

__global__ void combine_kernel() {
    int m = blockIdx.x * blockDim.x + threadIdx.x;
    if (m >= SEQ) return;
    float a = g_pmax[0][m], b = g_pmax[1][m];
    float gm = fmaxf(a, b);
    g_cadj[m] = gm + __logf(g_psum[0][m] * __expf(a - gm) + g_psum[1][m] * __expf(b - gm));
}

// ============================ pass B ========================================
// grid(64,2): 128 queries x 4096 keys. A = Q rows (persistent frags).
// Per 32-key chunk: S -> p=exp(s-cadj) -> split hi/lo -> smem P -> PV accum.
#define PB_Q      0u
#define PB_Q_LO   34816u
#define PB_K      69632u
#define PB_KSTG   17408u
#define PB_K_LO   8704u
#define PB_V      104448u
#define PB_VSTG   20480u
#define PB_V_LO   10240u
#define PB_P      145408u
#define PB_P_LO   10240u
#define PB_SMEM   165888

__global__ __launch_bounds__(256, 1)
void passB_kernel() {
    extern __shared__ char sm[];
    const uint32_t s0 = smem_u32(sm);
    const int tid = threadIdx.x, wid = tid >> 5, lane = tid & 31;
    const int q0 = blockIdx.x * 128, mbase = blockIdx.y * 4096;

    cp128(s0 + PB_Q,           g_Qh + q0 * HD, 128, tid);
    cp128(s0 + PB_Q + PB_Q_LO, g_Ql + q0 * HD, 128, tid);
    CP_COMMIT();
    cp128(s0 + PB_K,           g_Kh + mbase * HD, 32, tid);
    cp128(s0 + PB_K + PB_K_LO, g_Kl + mbase * HD, 32, tid);
    cpV(s0 + PB_V,           g_Vth + mbase, tid);
    cpV(s0 + PB_V + PB_V_LO, g_Vtl + mbase, tid);
    CP_COMMIT();
    CP_WAIT1();
    __syncthreads();

    uint32_t Qh[8][4], Ql[8][4];
    {
        uint32_t arow = (uint32_t)(wid * 16 + (lane & 7) + ((lane >> 3) & 1) * 8);
        uint32_t acol = (uint32_t)((lane >> 4) * 8);
        #pragma unroll
        for (int k = 0; k < 8; k++) {
            uint32_t a = s0 + PB_Q + arow * ST128 + (k * 16 + acol) * 2;
            LDSM4(Qh[k], a);
            LDSM4(Ql[k], a + PB_Q_LO);
        }
    }

    float Co[16][4];
    #pragma unroll
    for (int i = 0; i < 16; i++)
        #pragma unroll
        for (int j = 0; j < 4; j++) Co[i][j] = 0.0f;

    const uint32_t prow = (uint32_t)(wid * 16 + (lane >> 2));

    for (int ch = 0; ch < 128; ch++) {
        if (ch < 127) {
            int mc = mbase + (ch + 1) * 32;
            uint32_t kb = s0 + PB_K + (uint32_t)((ch + 1) & 1) * PB_KSTG;
            uint32_t vb = s0 + PB_V + (uint32_t)((ch + 1) & 1) * PB_VSTG;
            cp128(kb,           g_Kh + mc * HD, 32, tid);
            cp128(kb + PB_K_LO, g_Kl + mc * HD, 32, tid);
            cpV(vb,           g_Vth + mc, tid);
            cpV(vb + PB_V_LO, g_Vtl + mc, tid);
            CP_COMMIT();
            CP_WAIT1();
        } else CP_WAIT0();
        __syncthreads();

        const uint32_t kb = s0 + PB_K + (uint32_t)(ch & 1) * PB_KSTG;
        const uint32_t vb = s0 + PB_V + (uint32_t)(ch & 1) * PB_VSTG;
        const int mc = mbase + ch * 32;

        // ---- S tile + epilogue, 8 keys per n-group ----
        #pragma unroll
        for (int ns = 0; ns < 4; ns++) {
            float c[4] = {0.f, 0.f, 0.f, 0.f};
            #pragma unroll
            for (int kk = 0; kk < 4; kk++) {
                uint32_t Bh[4], Bl[4];
                uint32_t ba = kb + (uint32_t)(ns * 8 + (lane & 7)) * ST128
                                 + (uint32_t)(kk * 32 + ((lane >> 3) & 3) * 8) * 2;
                LDSM4(Bh, ba);
                LDSM4(Bl, ba + PB_K_LO);
                MMA(c, Qh[2*kk],   Bh[0], Bh[1]);
                MMA(c, Ql[2*kk],   Bh[0], Bh[1]);
                MMA(c, Qh[2*kk],   Bl[0], Bl[1]);
                MMA(c, Qh[2*kk+1], Bh[2], Bh[3]);
                MMA(c, Ql[2*kk+1], Bh[2], Bh[3]);
                MMA(c, Qh[2*kk+1], Bl[2], Bl[3]);
            }
            int col = ns * 8 + (lane & 3) * 2;
            float2 cj = *(const float2*)(g_cadj + mc + col);
            float p0 = __expf(c[0] - cj.x), p1 = __expf(c[1] - cj.y);
            float p2 = __expf(c[2] - cj.x), p3 = __expf(c[3] - cj.y);
            __nv_bfloat162 h01 = __floats2bfloat162_rn(p0, p1);
            __nv_bfloat162 h23 = __floats2bfloat162_rn(p2, p3);
            __nv_bfloat162 l01 = __floats2bfloat162_rn(p0 - __bfloat162float(h01.x),
                                                       p1 - __bfloat162float(h01.y));
            __nv_bfloat162 l23 = __floats2bfloat162_rn(p2 - __bfloat162float(h23.x),
                                                       p3 - __bfloat162float(h23.y));
            uint32_t po = PB_P + prow * ST32 + (uint32_t)col * 2;
            *(uint32_t*)(sm + po)                      = *(uint32_t*)&h01;
            *(uint32_t*)(sm + po + 8 * ST32)           = *(uint32_t*)&h23;
            *(uint32_t*)(sm + po + PB_P_LO)            = *(uint32_t*)&l01;
            *(uint32_t*)(sm + po + PB_P_LO + 8 * ST32) = *(uint32_t*)&l23;
        }
        __syncwarp();

        // ---- PV: A = P rows (warp-private 16 q rows), B = V^T [d][k] ----
        uint32_t PAh[2][4], PAl[2][4];
        {
            uint32_t arow = (uint32_t)(wid * 16 + (lane & 7) + ((lane >> 3) & 1) * 8);
            uint32_t acol = (uint32_t)((lane >> 4) * 8);
            #pragma unroll
            for (int ks = 0; ks < 2; ks++) {
                uint32_t a = s0 + PB_P + arow * ST32 + (ks * 16 + acol) * 2;
                LDSM4(PAh[ks], a);
                LDSM4(PAl[ks], a + PB_P_LO);
            }
        }
        #pragma unroll
        for (int ns = 0; ns < 16; ns++) {
            uint32_t Bh[4], Bl[4];
            uint32_t va = vb + (uint32_t)(ns * 8 + (lane & 7)) * ST32
                             + (uint32_t)((lane >> 3) * 8) * 2;
            LDSM4(Bh, va);
            LDSM4(Bl, va + PB_V_LO);
            MMA(Co[ns], PAh[0], Bh[0], Bh[1]);
            MMA(Co[ns], PAl[0], Bh[0], Bh[1]);
            MMA(Co[ns], PAh[0], Bl[0], Bl[1]);
            MMA(Co[ns], PAh[1], Bh[2], Bh[3]);
            MMA(Co[ns], PAl[1], Bh[2], Bh[3]);
            MMA(Co[ns], PAh[1], Bl[2], Bl[3]);
        }
        __syncthreads();
    }

    float* gp = g_part[blockIdx.y];
    int row0 = q0 + wid * 16 + (lane >> 2);
    #pragma unroll
    for (int ns = 0; ns < 16; ns++) {
        int col = ns * 8 + (lane & 3) * 2;
        *(float2*)(gp + (size_t)row0 * HD + col)       = make_float2(Co[ns][0], Co[ns][1]);
        *(float2*)(gp + (size_t)(row0 + 8) * HD + col) = make_float2(Co[ns][2], Co[ns][3]);
    }
}

__global__ void add_kernel(float* __restrict__ out) {
    int i = blockIdx.x * blockDim.x + threadIdx.x;
    float4 a = *(const float4*)(g_part[0] + (size_t)i * 4);
    float4 b = *(const float4*)(g_part[1] + (size_t)i * 4);
    *(float4*)(out + (size_t)i * 4) = make_float4(a.x + b.x, a.y + b.y, a.z + b.z, a.w + b.w);
}

// ---------------------------------------------------------------------------
extern "C" void kernel_launch(void* const* d_in, const int* in_sizes, int n_in,
                              void* d_out, int out_size) {
    (void)in_sizes; (void)n_in; (void)out_size;
    const float* Q = (const float*)d_in[0];
    const float* K = (const float*)d_in[1];
    const float* V = (const float*)d_in[2];
    float* out = (float*)d_out;

    cudaFuncSetAttribute(passA_kernel, cudaFuncAttributeMaxDynamicSharedMemorySize, PA_SMEM);
    cudaFuncSetAttribute(passB_kernel, cudaFuncAttributeMaxDynamicSharedMemorySize, PB_SMEM);

    conv_qk_kernel<<<SEQ * HD / 256, 256>>>(Q, K);
    conv_v_kernel<<<SEQ / 64, 128>>>(V);
    passA_kernel<<<dim3(64, 2), 256, PA_SMEM>>>();
    combine_kernel<<<SEQ / 256, 256>>>();
    passB_kernel<<<dim3(64, 2), 256, PB_SMEM>>>();
    add_kernel<<<SEQ * HD / 1024, 256>>>(out);
}